// round 2
// baseline (speedup 1.0000x reference)
#include <cuda_runtime.h>
#include <cuda_bf16.h>
#include <cstdint>
#include <cstddef>

// out[8192,4096] = x[8192,4096] @ quantize(W)^T * scale + bias
#define MROWS 8192
#define KDIM  4096
#define NDIM  4096

constexpr int BM = 128, BN = 128, BK = 32;
constexpr int NST = 4;
constexpr int KTILES = KDIM / BK;                 // 128
constexpr int TILE_A = BM * BK * 2;               // 8KB (one of hi/lo)
constexpr int TILE_B = BN * BK * 2;               // 8KB
constexpr int STAGE_BYTES = 2 * TILE_A + TILE_B;  // 24KB
constexpr int OFF_AH = 0;
constexpr int OFF_AL = TILE_A;
constexpr int OFF_B  = 2 * TILE_A;
constexpr int OFF_SCALE = NST * STAGE_BYTES;           // 96KB
constexpr int OFF_BIAS  = OFF_SCALE + BN * 4;
constexpr int SMEM_TOTAL = OFF_BIAS + BN * 4;          // 99328 B

// ---------------- static scratch (allocations forbidden) ----------------
__device__ __align__(16) __nv_bfloat16 g_XH[(size_t)MROWS * KDIM];  // 64 MB
__device__ __align__(16) __nv_bfloat16 g_XL[(size_t)MROWS * KDIM];  // 64 MB
__device__ __align__(16) __nv_bfloat16 g_Q [(size_t)NDIM  * KDIM];  // 32 MB

// ---------------- helpers (sm_80-level PTX only) ----------------
__device__ __forceinline__ uint32_t smem_u32(const void* p) {
    uint32_t a;
    asm("{ .reg .u64 t; cvta.to.shared.u64 t, %1; cvt.u32.u64 %0, t; }" : "=r"(a) : "l"(p));
    return a;
}
__device__ __forceinline__ void cp16(uint32_t dst, const void* src) {
    asm volatile("cp.async.cg.shared.global [%0], [%1], 16;" :: "r"(dst), "l"(src));
}
__device__ __forceinline__ void cp_commit() {
    asm volatile("cp.async.commit_group;" ::: "memory");
}
__device__ __forceinline__ uint32_t swz64(uint32_t off) {  // rows of 64B, 16B chunks
    return off ^ ((off >> 3) & 0x30);
}
__device__ __forceinline__ void ldm_x4(uint32_t* r, uint32_t addr) {
    asm volatile("ldmatrix.sync.aligned.m8n8.x4.shared.b16 {%0,%1,%2,%3}, [%4];"
                 : "=r"(r[0]), "=r"(r[1]), "=r"(r[2]), "=r"(r[3]) : "r"(addr));
}
__device__ __forceinline__ void mma_bf16(float* c, const uint32_t* a, const uint32_t* b) {
    asm volatile(
        "mma.sync.aligned.m16n8k16.row.col.f32.bf16.bf16.f32 "
        "{%0,%1,%2,%3}, {%4,%5,%6,%7}, {%8,%9}, {%0,%1,%2,%3};"
        : "+f"(c[0]), "+f"(c[1]), "+f"(c[2]), "+f"(c[3])
        : "r"(a[0]), "r"(a[1]), "r"(a[2]), "r"(a[3]), "r"(b[0]), "r"(b[1]));
}
__device__ __forceinline__ uint32_t pack2(float a, float b) {
    __nv_bfloat162 h = __floats2bfloat162_rn(a, b);
    return *reinterpret_cast<uint32_t*>(&h);
}

// ---------------- kernel 1: per-row alpha + ternary quantize -> bf16 ----------------
__global__ __launch_bounds__(256) void quantize_kernel(const float* __restrict__ W) {
    int row = blockIdx.x, tid = threadIdx.x;
    const float4* w4 = reinterpret_cast<const float4*>(W + (size_t)row * KDIM);
    float s = 0.f;
    #pragma unroll 4
    for (int i = tid; i < KDIM / 4; i += 256) {
        float4 v = w4[i];
        s += fabsf(v.x) + fabsf(v.y) + fabsf(v.z) + fabsf(v.w);
    }
    #pragma unroll
    for (int o = 16; o > 0; o >>= 1) s += __shfl_xor_sync(0xFFFFFFFFu, s, o);
    __shared__ float red[8];
    __shared__ float alphaS;
    if ((tid & 31) == 0) red[tid >> 5] = s;
    __syncthreads();
    if (tid == 0) {
        float t = 0.f;
        #pragma unroll
        for (int i = 0; i < 8; i++) t += red[i];
        alphaS = t / (float)KDIM;
    }
    __syncthreads();
    float alpha = alphaS;
    uint2* q2 = reinterpret_cast<uint2*>(g_Q + (size_t)row * KDIM);
    #pragma unroll 4
    for (int i = tid; i < KDIM / 4; i += 256) {
        float4 v = w4[i];
        float q0 = (v.x > alpha) ? 1.f : ((v.x < -alpha) ? -1.f : 0.f);
        float q1 = (v.y > alpha) ? 1.f : ((v.y < -alpha) ? -1.f : 0.f);
        float q2v = (v.z > alpha) ? 1.f : ((v.z < -alpha) ? -1.f : 0.f);
        float q3 = (v.w > alpha) ? 1.f : ((v.w < -alpha) ? -1.f : 0.f);
        uint2 o; o.x = pack2(q0, q1); o.y = pack2(q2v, q3);
        q2[i] = o;
    }
}

// ---------------- kernel 2: split x fp32 -> bf16 hi + bf16 lo (exact residual) ----------------
__global__ __launch_bounds__(256) void convert_kernel(const float* __restrict__ x) {
    const size_t n4 = (size_t)MROWS * KDIM / 4;
    const float4* x4 = reinterpret_cast<const float4*>(x);
    uint2* h4 = reinterpret_cast<uint2*>(g_XH);
    uint2* l4 = reinterpret_cast<uint2*>(g_XL);
    for (size_t i = (size_t)blockIdx.x * blockDim.x + threadIdx.x; i < n4;
         i += (size_t)gridDim.x * blockDim.x) {
        float4 v = x4[i];
        float h0 = __bfloat162float(__float2bfloat16(v.x));
        float h1 = __bfloat162float(__float2bfloat16(v.y));
        float h2 = __bfloat162float(__float2bfloat16(v.z));
        float h3 = __bfloat162float(__float2bfloat16(v.w));
        uint2 hh; hh.x = pack2(h0, h1);        hh.y = pack2(h2, h3);
        uint2 ll; ll.x = pack2(v.x - h0, v.y - h1); ll.y = pack2(v.z - h2, v.w - h3);
        h4[i] = hh;
        l4[i] = ll;
    }
}

// ---------------- stage copy: 1536 x 16B chunks over 256 threads ----------------
__device__ __forceinline__ void issue_copy(int mtile, int ntile, int kt, int s,
                                           uint32_t sb, int tid) {
    const char* xh = reinterpret_cast<const char*>(g_XH);
    const char* xl = reinterpret_cast<const char*>(g_XL);
    const char* qq = reinterpret_cast<const char*>(g_Q);
    const size_t rowB = (size_t)KDIM * 2;          // 8192 bytes
    const size_t kb = (size_t)kt * BK * 2;         // kt*64
    const size_t aBase = (size_t)(mtile * BM) * rowB + kb;
    const size_t bBase = (size_t)(ntile * BN) * rowB + kb;
    const uint32_t stage = sb + (uint32_t)s * STAGE_BYTES;
    #pragma unroll
    for (int i = 0; i < 2; i++) {               // A_hi: 512 chunks
        int c = tid + i * 256;
        int r = c >> 2, ch = c & 3;
        uint32_t off = swz64((uint32_t)(r * 64 + ch * 16));
        cp16(stage + OFF_AH + off, xh + aBase + (size_t)r * rowB + ch * 16);
    }
    #pragma unroll
    for (int i = 0; i < 2; i++) {               // A_lo
        int c = tid + i * 256;
        int r = c >> 2, ch = c & 3;
        uint32_t off = swz64((uint32_t)(r * 64 + ch * 16));
        cp16(stage + OFF_AL + off, xl + aBase + (size_t)r * rowB + ch * 16);
    }
    #pragma unroll
    for (int i = 0; i < 2; i++) {               // B (ternary bf16)
        int c = tid + i * 256;
        int r = c >> 2, ch = c & 3;
        uint32_t off = swz64((uint32_t)(r * 64 + ch * 16));
        cp16(stage + OFF_B + off, qq + bBase + (size_t)r * rowB + ch * 16);
    }
}

// ---------------- kernel 3: 4-stage cp.async pipelined HMMA GEMM ----------------
__global__ __launch_bounds__(256, 1) void gemm_kernel(const float* __restrict__ scale,
                                                      const float* __restrict__ bias,
                                                      float* __restrict__ out) {
    extern __shared__ __align__(1024) char smem[];
    const uint32_t sb = smem_u32(smem);
    const int tid = threadIdx.x;
    const int wid = tid >> 5;
    const int lid = tid & 31;
    const int ntile = blockIdx.x;   // 32
    const int mtile = blockIdx.y;   // 64

    const int warp_m = wid & 3;     // 4 warps along M: 32 rows each
    const int warp_n = wid >> 2;    // 2 warps along N: 64 cols each

    float* s_scale = reinterpret_cast<float*>(smem + OFF_SCALE);
    float* s_bias  = reinterpret_cast<float*>(smem + OFF_BIAS);
    if (tid < BN) {
        s_scale[tid] = scale[ntile * BN + tid];
        s_bias[tid]  = bias[ntile * BN + tid];
    }

    float acc[2][8][4];
    #pragma unroll
    for (int mi = 0; mi < 2; mi++)
        #pragma unroll
        for (int ni = 0; ni < 8; ni++)
            #pragma unroll
            for (int k = 0; k < 4; k++) acc[mi][ni][k] = 0.f;

    // prologue: stages 0..2 in flight
    issue_copy(mtile, ntile, 0, 0, sb, tid); cp_commit();
    issue_copy(mtile, ntile, 1, 1, sb, tid); cp_commit();
    issue_copy(mtile, ntile, 2, 2, sb, tid); cp_commit();

    // ldmatrix lane address components
    const int lane15 = lid & 15;
    const int laneHiA = lid >> 4;                       // A: second k8 chunk
    const int rowBl = (lid & 7) + ((lid >> 4) & 1) * 8; // B: row within n16 group
    const int chBl  = (lid >> 3) & 1;                   // B: k8 chunk select

    for (int kt = 0; kt < KTILES; kt++) {
        asm volatile("cp.async.wait_group 2;" ::: "memory");
        __syncthreads();

        const int j = kt + 3;
        if (j < KTILES) issue_copy(mtile, ntile, j, j & 3, sb, tid);
        cp_commit();

        const uint32_t stage = sb + (uint32_t)(kt & 3) * STAGE_BYTES;

        #pragma unroll
        for (int k16 = 0; k16 < 2; k16++) {
            uint32_t ah[2][4], al[2][4], bf[8][2];
            #pragma unroll
            for (int mi = 0; mi < 2; mi++) {
                uint32_t off = (uint32_t)((warp_m * 32 + mi * 16 + lane15) * 64 +
                                          (k16 * 2 + laneHiA) * 16);
                ldm_x4(ah[mi], stage + OFF_AH + swz64(off));
                ldm_x4(al[mi], stage + OFF_AL + swz64(off));
            }
            #pragma unroll
            for (int nq = 0; nq < 4; nq++) {
                uint32_t off = (uint32_t)((warp_n * 64 + nq * 16 + rowBl) * 64 +
                                          (k16 * 2 + chBl) * 16);
                uint32_t r[4];
                ldm_x4(r, stage + OFF_B + swz64(off));
                bf[nq * 2 + 0][0] = r[0]; bf[nq * 2 + 0][1] = r[1];
                bf[nq * 2 + 1][0] = r[2]; bf[nq * 2 + 1][1] = r[3];
            }
            #pragma unroll
            for (int mi = 0; mi < 2; mi++)
                #pragma unroll
                for (int ni = 0; ni < 8; ni++) {
                    mma_bf16(acc[mi][ni], ah[mi], bf[ni]);
                    mma_bf16(acc[mi][ni], al[mi], bf[ni]);
                }
        }
    }

    __syncthreads();   // s_scale/s_bias visible (written at entry)

    // epilogue: scale/bias + direct stores (float2 per row-half)
    const int qrow = lid >> 2;
    const int qcol = (lid & 3) * 2;
    #pragma unroll
    for (int mi = 0; mi < 2; mi++) {
        #pragma unroll
        for (int ni = 0; ni < 8; ni++) {
            const int colL = warp_n * 64 + ni * 8 + qcol;      // CTA-local col
            const float s0 = s_scale[colL], s1 = s_scale[colL + 1];
            const float b0 = s_bias[colL],  b1 = s_bias[colL + 1];
            const int gcol = ntile * BN + colL;
            const int grow0 = mtile * BM + warp_m * 32 + mi * 16 + qrow;
            float2 v0, v1;
            v0.x = acc[mi][ni][0] * s0 + b0;
            v0.y = acc[mi][ni][1] * s1 + b1;
            v1.x = acc[mi][ni][2] * s0 + b0;
            v1.y = acc[mi][ni][3] * s1 + b1;
            *reinterpret_cast<float2*>(out + (size_t)grow0 * NDIM + gcol) = v0;
            *reinterpret_cast<float2*>(out + (size_t)(grow0 + 8) * NDIM + gcol) = v1;
        }
    }
}

// ---------------- launch ----------------
extern "C" void kernel_launch(void* const* d_in, const int* in_sizes, int n_in,
                              void* d_out, int out_size) {
    const float* x      = (const float*)d_in[0];
    const float* weight = (const float*)d_in[1];
    const float* scale  = (const float*)d_in[2];
    const float* bias   = (const float*)d_in[3];
    float* out = (float*)d_out;

    quantize_kernel<<<NDIM, 256>>>(weight);
    convert_kernel<<<4096, 256>>>(x);

    cudaFuncSetAttribute(gemm_kernel, cudaFuncAttributeMaxDynamicSharedMemorySize, SMEM_TOTAL);
    dim3 grid(NDIM / BN, MROWS / BM);   // 32 x 64; x-major wave keeps full B panel in L2
    gemm_kernel<<<grid, 256, SMEM_TOTAL>>>(scale, bias, out);
}

// round 3
// speedup vs baseline: 1.9422x; 1.9422x over previous
#include <cuda_runtime.h>
#include <cuda_bf16.h>
#include <cuda_fp16.h>
#include <cstdint>
#include <cstddef>

// out[8192,4096] = x[8192,4096] @ quantize(W)^T * scale + bias
#define MROWS 8192
#define KDIM  4096
#define NDIM  4096

constexpr int BM = 128, BN = 128, BK = 64;
constexpr int NST = 4;
constexpr int KTILES = KDIM / BK;                 // 64
constexpr int TILE_A = BM * BK * 2;               // 16KB
constexpr int TILE_B = BN * BK * 2;               // 16KB
constexpr int STAGE_BYTES = TILE_A + TILE_B;      // 32KB
constexpr int OFF_A = 0;
constexpr int OFF_B = TILE_A;
constexpr int OFF_SCALE = NST * STAGE_BYTES;      // 128KB
constexpr int OFF_BIAS  = OFF_SCALE + BN * 4;
constexpr int SMEM_TOTAL = OFF_BIAS + BN * 4;     // 132096 B

// ---------------- static scratch (allocations forbidden) ----------------
__device__ __align__(16) __half g_XF[(size_t)MROWS * KDIM];  // 64 MB fp16 x
__device__ __align__(16) __half g_Q [(size_t)NDIM  * KDIM];  // 32 MB fp16 ternary

// ---------------- helpers (sm_80-level PTX only) ----------------
__device__ __forceinline__ uint32_t smem_u32(const void* p) {
    uint32_t a;
    asm("{ .reg .u64 t; cvta.to.shared.u64 t, %1; cvt.u32.u64 %0, t; }" : "=r"(a) : "l"(p));
    return a;
}
__device__ __forceinline__ void cp16(uint32_t dst, const void* src) {
    asm volatile("cp.async.cg.shared.global [%0], [%1], 16;" :: "r"(dst), "l"(src));
}
__device__ __forceinline__ void cp_commit() {
    asm volatile("cp.async.commit_group;" ::: "memory");
}
// SW128 for 128-byte rows: chunk(16B) index ^= (row & 7)
__device__ __forceinline__ uint32_t swz128(uint32_t off) {
    return off ^ ((off >> 3) & 0x70);
}
__device__ __forceinline__ void ldm_x4(uint32_t* r, uint32_t addr) {
    asm volatile("ldmatrix.sync.aligned.m8n8.x4.shared.b16 {%0,%1,%2,%3}, [%4];"
                 : "=r"(r[0]), "=r"(r[1]), "=r"(r[2]), "=r"(r[3]) : "r"(addr));
}
__device__ __forceinline__ void mma_fp16(float* c, const uint32_t* a, const uint32_t* b) {
    asm volatile(
        "mma.sync.aligned.m16n8k16.row.col.f32.f16.f16.f32 "
        "{%0,%1,%2,%3}, {%4,%5,%6,%7}, {%8,%9}, {%0,%1,%2,%3};"
        : "+f"(c[0]), "+f"(c[1]), "+f"(c[2]), "+f"(c[3])
        : "r"(a[0]), "r"(a[1]), "r"(a[2]), "r"(a[3]), "r"(b[0]), "r"(b[1]));
}
__device__ __forceinline__ uint32_t packh2(float a, float b) {
    __half2 h = __floats2half2_rn(a, b);
    return *reinterpret_cast<uint32_t*>(&h);
}

// ---------------- kernel 1: per-row alpha + ternary quantize -> fp16 ----------------
__global__ __launch_bounds__(256) void quantize_kernel(const float* __restrict__ W) {
    int row = blockIdx.x, tid = threadIdx.x;
    const float4* w4 = reinterpret_cast<const float4*>(W + (size_t)row * KDIM);
    float s = 0.f;
    #pragma unroll 4
    for (int i = tid; i < KDIM / 4; i += 256) {
        float4 v = w4[i];
        s += fabsf(v.x) + fabsf(v.y) + fabsf(v.z) + fabsf(v.w);
    }
    #pragma unroll
    for (int o = 16; o > 0; o >>= 1) s += __shfl_xor_sync(0xFFFFFFFFu, s, o);
    __shared__ float red[8];
    __shared__ float alphaS;
    if ((tid & 31) == 0) red[tid >> 5] = s;
    __syncthreads();
    if (tid == 0) {
        float t = 0.f;
        #pragma unroll
        for (int i = 0; i < 8; i++) t += red[i];
        alphaS = t / (float)KDIM;
    }
    __syncthreads();
    float alpha = alphaS;
    uint2* q2 = reinterpret_cast<uint2*>(g_Q + (size_t)row * KDIM);
    #pragma unroll 4
    for (int i = tid; i < KDIM / 4; i += 256) {
        float4 v = w4[i];
        float q0 = (v.x > alpha) ? 1.f : ((v.x < -alpha) ? -1.f : 0.f);
        float q1 = (v.y > alpha) ? 1.f : ((v.y < -alpha) ? -1.f : 0.f);
        float q2v = (v.z > alpha) ? 1.f : ((v.z < -alpha) ? -1.f : 0.f);
        float q3 = (v.w > alpha) ? 1.f : ((v.w < -alpha) ? -1.f : 0.f);
        uint2 o; o.x = packh2(q0, q1); o.y = packh2(q2v, q3);
        q2[i] = o;
    }
}

// ---------------- kernel 2: x fp32 -> fp16 ----------------
__global__ __launch_bounds__(256) void convert_kernel(const float* __restrict__ x) {
    const size_t n4 = (size_t)MROWS * KDIM / 4;
    const float4* x4 = reinterpret_cast<const float4*>(x);
    uint2* h4 = reinterpret_cast<uint2*>(g_XF);
    for (size_t i = (size_t)blockIdx.x * blockDim.x + threadIdx.x; i < n4;
         i += (size_t)gridDim.x * blockDim.x) {
        float4 v = x4[i];
        uint2 hh; hh.x = packh2(v.x, v.y); hh.y = packh2(v.z, v.w);
        h4[i] = hh;
    }
}

// ---------------- stage copy: 2048 x 16B chunks over 256 threads ----------------
__device__ __forceinline__ void issue_copy(int mtile, int ntile, int kt, int s,
                                           uint32_t sb, int tid) {
    const char* xf = reinterpret_cast<const char*>(g_XF);
    const char* qq = reinterpret_cast<const char*>(g_Q);
    const size_t rowB = (size_t)KDIM * 2;          // 8192 bytes
    const size_t kb = (size_t)kt * BK * 2;         // kt*128
    const size_t aBase = (size_t)(mtile * BM) * rowB + kb;
    const size_t bBase = (size_t)(ntile * BN) * rowB + kb;
    const uint32_t stage = sb + (uint32_t)s * STAGE_BYTES;
    #pragma unroll
    for (int i = 0; i < 4; i++) {               // A: 1024 chunks (128 rows x 8)
        int c = tid + i * 256;
        int r = c >> 3, ch = c & 7;
        uint32_t off = swz128((uint32_t)(r * 128 + ch * 16));
        cp16(stage + OFF_A + off, xf + aBase + (size_t)r * rowB + ch * 16);
    }
    #pragma unroll
    for (int i = 0; i < 4; i++) {               // B: 1024 chunks
        int c = tid + i * 256;
        int r = c >> 3, ch = c & 7;
        uint32_t off = swz128((uint32_t)(r * 128 + ch * 16));
        cp16(stage + OFF_B + off, qq + bBase + (size_t)r * rowB + ch * 16);
    }
}

// ---------------- kernel 3: 4-stage cp.async pipelined fp16 HMMA GEMM ----------------
__global__ __launch_bounds__(256, 1) void gemm_kernel(const float* __restrict__ scale,
                                                      const float* __restrict__ bias,
                                                      float* __restrict__ out) {
    extern __shared__ __align__(1024) char smem[];
    const uint32_t sb = smem_u32(smem);
    const int tid = threadIdx.x;
    const int wid = tid >> 5;
    const int lid = tid & 31;
    const int ntile = blockIdx.x;   // 32
    const int mtile = blockIdx.y;   // 64

    const int warp_m = wid & 3;     // 4 warps along M: 32 rows each
    const int warp_n = wid >> 2;    // 2 warps along N: 64 cols each

    float* s_scale = reinterpret_cast<float*>(smem + OFF_SCALE);
    float* s_bias  = reinterpret_cast<float*>(smem + OFF_BIAS);
    if (tid < BN) {
        s_scale[tid] = scale[ntile * BN + tid];
        s_bias[tid]  = bias[ntile * BN + tid];
    }

    float acc[2][8][4];
    #pragma unroll
    for (int mi = 0; mi < 2; mi++)
        #pragma unroll
        for (int ni = 0; ni < 8; ni++)
            #pragma unroll
            for (int k = 0; k < 4; k++) acc[mi][ni][k] = 0.f;

    // prologue: stages 0..2 in flight
    issue_copy(mtile, ntile, 0, 0, sb, tid); cp_commit();
    issue_copy(mtile, ntile, 1, 1, sb, tid); cp_commit();
    issue_copy(mtile, ntile, 2, 2, sb, tid); cp_commit();

    // ldmatrix lane address components
    const int lane15 = lid & 15;
    const int laneHiA = lid >> 4;                       // A: second k8 chunk
    const int rowBl = (lid & 7) + ((lid >> 4) & 1) * 8; // B: row within n16 group
    const int chBl  = (lid >> 3) & 1;                   // B: k8 chunk select

    for (int kt = 0; kt < KTILES; kt++) {
        asm volatile("cp.async.wait_group 2;" ::: "memory");
        __syncthreads();

        const int j = kt + 3;
        if (j < KTILES) issue_copy(mtile, ntile, j, j & 3, sb, tid);
        cp_commit();

        const uint32_t stage = sb + (uint32_t)(kt & 3) * STAGE_BYTES;

        #pragma unroll
        for (int k16 = 0; k16 < 4; k16++) {
            uint32_t af[2][4], bf[8][2];
            #pragma unroll
            for (int mi = 0; mi < 2; mi++) {
                uint32_t off = (uint32_t)((warp_m * 32 + mi * 16 + lane15) * 128 +
                                          k16 * 32 + laneHiA * 16);
                ldm_x4(af[mi], stage + OFF_A + swz128(off));
            }
            #pragma unroll
            for (int nq = 0; nq < 4; nq++) {
                uint32_t off = (uint32_t)((warp_n * 64 + nq * 16 + rowBl) * 128 +
                                          k16 * 32 + chBl * 16);
                uint32_t r[4];
                ldm_x4(r, stage + OFF_B + swz128(off));
                bf[nq * 2 + 0][0] = r[0]; bf[nq * 2 + 0][1] = r[1];
                bf[nq * 2 + 1][0] = r[2]; bf[nq * 2 + 1][1] = r[3];
            }
            #pragma unroll
            for (int mi = 0; mi < 2; mi++)
                #pragma unroll
                for (int ni = 0; ni < 8; ni++)
                    mma_fp16(acc[mi][ni], af[mi], bf[ni]);
        }
    }

    __syncthreads();   // s_scale/s_bias visible

    // epilogue: scale/bias + direct float2 stores
    const int qrow = lid >> 2;
    const int qcol = (lid & 3) * 2;
    #pragma unroll
    for (int mi = 0; mi < 2; mi++) {
        #pragma unroll
        for (int ni = 0; ni < 8; ni++) {
            const int colL = warp_n * 64 + ni * 8 + qcol;      // CTA-local col
            const float s0 = s_scale[colL], s1 = s_scale[colL + 1];
            const float b0 = s_bias[colL],  b1 = s_bias[colL + 1];
            const int gcol = ntile * BN + colL;
            const int grow0 = mtile * BM + warp_m * 32 + mi * 16 + qrow;
            float2 v0, v1;
            v0.x = acc[mi][ni][0] * s0 + b0;
            v0.y = acc[mi][ni][1] * s1 + b1;
            v1.x = acc[mi][ni][2] * s0 + b0;
            v1.y = acc[mi][ni][3] * s1 + b1;
            *reinterpret_cast<float2*>(out + (size_t)grow0 * NDIM + gcol) = v0;
            *reinterpret_cast<float2*>(out + (size_t)(grow0 + 8) * NDIM + gcol) = v1;
        }
    }
}

// ---------------- launch ----------------
extern "C" void kernel_launch(void* const* d_in, const int* in_sizes, int n_in,
                              void* d_out, int out_size) {
    const float* x      = (const float*)d_in[0];
    const float* weight = (const float*)d_in[1];
    const float* scale  = (const float*)d_in[2];
    const float* bias   = (const float*)d_in[3];
    float* out = (float*)d_out;

    quantize_kernel<<<NDIM, 256>>>(weight);
    convert_kernel<<<8192, 256>>>(x);

    cudaFuncSetAttribute(gemm_kernel, cudaFuncAttributeMaxDynamicSharedMemorySize, SMEM_TOTAL);
    dim3 grid(NDIM / BN, MROWS / BM);   // 32 x 64; x-major wave keeps B panel in L2
    gemm_kernel<<<grid, 256, SMEM_TOTAL>>>(scale, bias, out);
}

// round 4
// speedup vs baseline: 2.2818x; 1.1749x over previous
#include <cuda_runtime.h>
#include <cuda_bf16.h>
#include <cuda_fp16.h>
#include <cstdint>
#include <cstddef>

// out[8192,4096] = x[8192,4096] @ quantize(W)^T * scale + bias
#define MROWS 8192
#define KDIM  4096
#define NDIM  4096

constexpr int BM = 128, BN = 256, BK = 64;
constexpr int NST = 4;
constexpr int KTILES = KDIM / BK;                 // 64
constexpr int TILE_A = BM * BK * 2;               // 16KB
constexpr int TILE_B = BN * BK * 2;               // 32KB
constexpr int STAGE_BYTES = TILE_A + TILE_B;      // 48KB
constexpr int OFF_A = 0;
constexpr int OFF_B = TILE_A;
constexpr int OFF_SCALE = NST * STAGE_BYTES;      // 192KB
constexpr int OFF_BIAS  = OFF_SCALE + BN * 4;
constexpr int SMEM_TOTAL = OFF_BIAS + BN * 4;     // 198656 B < 227KB

// ---------------- static scratch (allocations forbidden) ----------------
__device__ __align__(16) __half g_XF[(size_t)MROWS * KDIM];  // 64 MB fp16 x
__device__ __align__(16) __half g_Q [(size_t)NDIM  * KDIM];  // 32 MB fp16 ternary

// ---------------- helpers (sm_80-level PTX only) ----------------
__device__ __forceinline__ uint32_t smem_u32(const void* p) {
    uint32_t a;
    asm("{ .reg .u64 t; cvta.to.shared.u64 t, %1; cvt.u32.u64 %0, t; }" : "=r"(a) : "l"(p));
    return a;
}
__device__ __forceinline__ void cp16(uint32_t dst, const void* src) {
    asm volatile("cp.async.cg.shared.global [%0], [%1], 16;" :: "r"(dst), "l"(src));
}
__device__ __forceinline__ void cp_commit() {
    asm volatile("cp.async.commit_group;" ::: "memory");
}
// SW128 for 128-byte rows
__device__ __forceinline__ uint32_t swz128(uint32_t off) {
    return off ^ ((off >> 3) & 0x70);
}
__device__ __forceinline__ void ldm_x4(uint32_t* r, uint32_t addr) {
    asm volatile("ldmatrix.sync.aligned.m8n8.x4.shared.b16 {%0,%1,%2,%3}, [%4];"
                 : "=r"(r[0]), "=r"(r[1]), "=r"(r[2]), "=r"(r[3]) : "r"(addr));
}
__device__ __forceinline__ void mma_fp16(float* c, const uint32_t* a, const uint32_t* b) {
    asm volatile(
        "mma.sync.aligned.m16n8k16.row.col.f32.f16.f16.f32 "
        "{%0,%1,%2,%3}, {%4,%5,%6,%7}, {%8,%9}, {%0,%1,%2,%3};"
        : "+f"(c[0]), "+f"(c[1]), "+f"(c[2]), "+f"(c[3])
        : "r"(a[0]), "r"(a[1]), "r"(a[2]), "r"(a[3]), "r"(b[0]), "r"(b[1]));
}
__device__ __forceinline__ uint32_t packh2(float a, float b) {
    __half2 h = __floats2half2_rn(a, b);
    return *reinterpret_cast<uint32_t*>(&h);
}

// ---------------- kernel 1: per-row alpha + ternary quantize -> fp16 ----------------
__global__ __launch_bounds__(256) void quantize_kernel(const float* __restrict__ W) {
    int row = blockIdx.x, tid = threadIdx.x;
    const float4* w4 = reinterpret_cast<const float4*>(W + (size_t)row * KDIM);
    float s = 0.f;
    #pragma unroll 4
    for (int i = tid; i < KDIM / 4; i += 256) {
        float4 v = w4[i];
        s += fabsf(v.x) + fabsf(v.y) + fabsf(v.z) + fabsf(v.w);
    }
    #pragma unroll
    for (int o = 16; o > 0; o >>= 1) s += __shfl_xor_sync(0xFFFFFFFFu, s, o);
    __shared__ float red[8];
    __shared__ float alphaS;
    if ((tid & 31) == 0) red[tid >> 5] = s;
    __syncthreads();
    if (tid == 0) {
        float t = 0.f;
        #pragma unroll
        for (int i = 0; i < 8; i++) t += red[i];
        alphaS = t / (float)KDIM;
    }
    __syncthreads();
    float alpha = alphaS;
    uint2* q2 = reinterpret_cast<uint2*>(g_Q + (size_t)row * KDIM);
    #pragma unroll 4
    for (int i = tid; i < KDIM / 4; i += 256) {
        float4 v = w4[i];
        float q0 = (v.x > alpha) ? 1.f : ((v.x < -alpha) ? -1.f : 0.f);
        float q1 = (v.y > alpha) ? 1.f : ((v.y < -alpha) ? -1.f : 0.f);
        float q2v = (v.z > alpha) ? 1.f : ((v.z < -alpha) ? -1.f : 0.f);
        float q3 = (v.w > alpha) ? 1.f : ((v.w < -alpha) ? -1.f : 0.f);
        uint2 o; o.x = packh2(q0, q1); o.y = packh2(q2v, q3);
        q2[i] = o;
    }
}

// ---------------- kernel 2: x fp32 -> fp16 ----------------
__global__ __launch_bounds__(256) void convert_kernel(const float* __restrict__ x) {
    const size_t n4 = (size_t)MROWS * KDIM / 4;
    const float4* x4 = reinterpret_cast<const float4*>(x);
    uint2* h4 = reinterpret_cast<uint2*>(g_XF);
    for (size_t i = (size_t)blockIdx.x * blockDim.x + threadIdx.x; i < n4;
         i += (size_t)gridDim.x * blockDim.x) {
        float4 v = x4[i];
        uint2 hh; hh.x = packh2(v.x, v.y); hh.y = packh2(v.z, v.w);
        h4[i] = hh;
    }
}

// ---------------- stage copy: 3072 x 16B chunks over 256 threads ----------------
__device__ __forceinline__ void issue_copy(int mtile, int ntile, int kt, int s,
                                           uint32_t sb, int tid) {
    const char* xf = reinterpret_cast<const char*>(g_XF);
    const char* qq = reinterpret_cast<const char*>(g_Q);
    const size_t rowB = (size_t)KDIM * 2;          // 8192 bytes
    const size_t kb = (size_t)kt * BK * 2;         // kt*128
    const size_t aBase = (size_t)(mtile * BM) * rowB + kb;
    const size_t bBase = (size_t)(ntile * BN) * rowB + kb;
    const uint32_t stage = sb + (uint32_t)s * STAGE_BYTES;
    #pragma unroll
    for (int i = 0; i < 4; i++) {               // A: 1024 chunks (128 rows x 8)
        int c = tid + i * 256;
        int r = c >> 3, ch = c & 7;
        uint32_t off = swz128((uint32_t)(r * 128 + ch * 16));
        cp16(stage + OFF_A + off, xf + aBase + (size_t)r * rowB + ch * 16);
    }
    #pragma unroll
    for (int i = 0; i < 8; i++) {               // B: 2048 chunks (256 rows x 8)
        int c = tid + i * 256;
        int r = c >> 3, ch = c & 7;
        uint32_t off = swz128((uint32_t)(r * 128 + ch * 16));
        cp16(stage + OFF_B + off, qq + bBase + (size_t)r * rowB + ch * 16);
    }
}

// ---------------- kernel 3: 4-stage cp.async fp16 HMMA GEMM, 128x256 tile ----------------
__global__ __launch_bounds__(256, 1) void gemm_kernel(const float* __restrict__ scale,
                                                      const float* __restrict__ bias,
                                                      float* __restrict__ out) {
    extern __shared__ __align__(1024) char smem[];
    const uint32_t sb = smem_u32(smem);
    const int tid = threadIdx.x;
    const int wid = tid >> 5;
    const int lid = tid & 31;
    const int ntile = blockIdx.x;   // 16
    const int mtile = blockIdx.y;   // 64

    const int warp_m = wid >> 2;    // 2 warps along M: 64 rows each
    const int warp_n = wid & 3;     // 4 warps along N: 64 cols each

    float* s_scale = reinterpret_cast<float*>(smem + OFF_SCALE);
    float* s_bias  = reinterpret_cast<float*>(smem + OFF_BIAS);
    s_scale[tid] = scale[ntile * BN + tid];
    s_bias[tid]  = bias[ntile * BN + tid];

    float acc[4][8][4];
    #pragma unroll
    for (int mi = 0; mi < 4; mi++)
        #pragma unroll
        for (int ni = 0; ni < 8; ni++)
            #pragma unroll
            for (int k = 0; k < 4; k++) acc[mi][ni][k] = 0.f;

    // prologue: stages 0..2 in flight
    issue_copy(mtile, ntile, 0, 0, sb, tid); cp_commit();
    issue_copy(mtile, ntile, 1, 1, sb, tid); cp_commit();
    issue_copy(mtile, ntile, 2, 2, sb, tid); cp_commit();

    // ldmatrix lane address components
    const int lane15 = lid & 15;
    const int laneHiA = lid >> 4;                       // A: k8 chunk select
    const int rowBl = (lid & 7) + ((lid >> 4) & 1) * 8; // B: row within n16 group
    const int chBl  = (lid >> 3) & 1;                   // B: k8 chunk select

    // double-buffered fragments
    uint32_t af[2][4][4];   // [buf][m16 tile][regs]
    uint32_t bf[2][4][4];   // [buf][n16 tile][regs]; regs 0,1 = first n8; 2,3 = second

    const uint32_t aAddrBase = (uint32_t)((warp_m * 64 + lane15) * 128 + laneHiA * 16);
    const uint32_t bAddrBase = (uint32_t)((warp_n * 64 + rowBl) * 128 + chBl * 16);

    for (int kt = 0; kt < KTILES; kt++) {
        asm volatile("cp.async.wait_group 2;" ::: "memory");
        __syncthreads();

        const int j = kt + 3;
        if (j < KTILES) issue_copy(mtile, ntile, j, j & 3, sb, tid);
        cp_commit();

        const uint32_t stage = sb + (uint32_t)(kt & 3) * STAGE_BYTES;
        const uint32_t aS = stage + OFF_A;
        const uint32_t bS = stage + OFF_B;

        // load fragments for k16=0 into buffer 0
        #pragma unroll
        for (int mi = 0; mi < 4; mi++)
            ldm_x4(af[0][mi], aS + swz128(aAddrBase + (uint32_t)(mi * 16 * 128)));
        #pragma unroll
        for (int nq = 0; nq < 4; nq++)
            ldm_x4(bf[0][nq], bS + swz128(bAddrBase + (uint32_t)(nq * 16 * 128)));

        #pragma unroll
        for (int k16 = 0; k16 < 4; k16++) {
            const int cur = k16 & 1;
            if (k16 < 3) {                          // prefetch next k16
                const int nxt = cur ^ 1;
                const uint32_t kOff = (uint32_t)((k16 + 1) * 32);
                #pragma unroll
                for (int mi = 0; mi < 4; mi++)
                    ldm_x4(af[nxt][mi],
                           aS + swz128(aAddrBase + kOff + (uint32_t)(mi * 16 * 128)));
                #pragma unroll
                for (int nq = 0; nq < 4; nq++)
                    ldm_x4(bf[nxt][nq],
                           bS + swz128(bAddrBase + kOff + (uint32_t)(nq * 16 * 128)));
            }
            #pragma unroll
            for (int mi = 0; mi < 4; mi++)
                #pragma unroll
                for (int ni = 0; ni < 8; ni++)
                    mma_fp16(acc[mi][ni], af[cur][mi], &bf[cur][ni >> 1][(ni & 1) * 2]);
        }
    }

    __syncthreads();   // s_scale/s_bias visible

    // epilogue: scale/bias + direct float2 stores
    const int qrow = lid >> 2;
    const int qcol = (lid & 3) * 2;
    #pragma unroll
    for (int mi = 0; mi < 4; mi++) {
        #pragma unroll
        for (int ni = 0; ni < 8; ni++) {
            const int colL = warp_n * 64 + ni * 8 + qcol;      // CTA-local col
            const float s0 = s_scale[colL], s1 = s_scale[colL + 1];
            const float b0 = s_bias[colL],  b1 = s_bias[colL + 1];
            const int gcol = ntile * BN + colL;
            const int grow0 = mtile * BM + warp_m * 64 + mi * 16 + qrow;
            float2 v0, v1;
            v0.x = acc[mi][ni][0] * s0 + b0;
            v0.y = acc[mi][ni][1] * s1 + b1;
            v1.x = acc[mi][ni][2] * s0 + b0;
            v1.y = acc[mi][ni][3] * s1 + b1;
            *reinterpret_cast<float2*>(out + (size_t)grow0 * NDIM + gcol) = v0;
            *reinterpret_cast<float2*>(out + (size_t)(grow0 + 8) * NDIM + gcol) = v1;
        }
    }
}

// ---------------- launch ----------------
extern "C" void kernel_launch(void* const* d_in, const int* in_sizes, int n_in,
                              void* d_out, int out_size) {
    const float* x      = (const float*)d_in[0];
    const float* weight = (const float*)d_in[1];
    const float* scale  = (const float*)d_in[2];
    const float* bias   = (const float*)d_in[3];
    float* out = (float*)d_out;

    quantize_kernel<<<NDIM, 256>>>(weight);
    convert_kernel<<<8192, 256>>>(x);

    cudaFuncSetAttribute(gemm_kernel, cudaFuncAttributeMaxDynamicSharedMemorySize, SMEM_TOTAL);
    dim3 grid(NDIM / BN, MROWS / BM);   // 16 x 64; x-major wave keeps B panel in L2
    gemm_kernel<<<grid, 256, SMEM_TOTAL>>>(scale, bias, out);
}